// round 15
// baseline (speedup 1.0000x reference)
#include <cuda_runtime.h>
#include <cuda_bf16.h>
#include <cstdint>

// Problem constants
#define NTOT 131072
#define NB   2048
#define NF   200
#define GDIM 800
#define STEPS 3

// bf16x3 via K-concatenation: W = [bH | bH | bL] (3 sections),
// A stored deduped as [aH | aL] (2 sections); chunk c>=2*SECC remaps to aH.
#define KB1 1920
#define KB2 1344
#define KA1 1280
#define KA2 896
#define SEC1 640
#define SEC2 448
#define SECC1 10         // chunks (of 64) per section, step 1
#define SECC2 7
#define NCH1 30
#define NCH2 21
#define GM 128
#define GNT 80
#define NSPLIT 2
#define NSTAGE 2
#define STG 26624        // A 128x64 bf16 (16384) + B 80x64 bf16 (10240)
#define SOFF 1024
#define ESHIFT 16.0f     // constant softmax shift (exact algebra, overflow guard)

// ---------------- scratch ----------------------------------------------------
__device__ __nv_bfloat16 g_Zb1[NB * KA1];
__device__ __nv_bfloat16 g_Zb2[NB * KA2];
__device__ __nv_bfloat16 g_Wb1[GDIM * KB1];   // permuted rows jp = unit*4+gate
__device__ __nv_bfloat16 g_Wb2[GDIM * KB2];
__device__ float g_biasP[GDIM];
__device__ float g_C[NB * NF];                // LSTM cell state
__device__ float g_Gp[NSPLIT * NB * GDIM];    // split-K partials
__device__ int   g_seg[NB + 2];

// ---------------- helpers ----------------------------------------------------
__device__ __forceinline__ uint32_t smem_u32(const void* p) {
    return (uint32_t)__cvta_generic_to_shared(p);
}
__device__ __forceinline__ float sigmoidf_(float x) { return 1.0f / (1.0f + expf(-x)); }

__device__ __forceinline__ void cp16cg(uint32_t dst, const void* src) {
    asm volatile("cp.async.cg.shared.global [%0], [%1], 16;" :: "r"(dst), "l"(src) : "memory");
}
// L1-enabled variant: co-resident CTAs (same SM) share the A tile → L1 hits
__device__ __forceinline__ void cp16ca(uint32_t dst, const void* src) {
    asm volatile("cp.async.ca.shared.global [%0], [%1], 16;" :: "r"(dst), "l"(src) : "memory");
}
#define CP_COMMIT() asm volatile("cp.async.commit_group;" ::: "memory")

__device__ __forceinline__ float4 ld4(const float* p) {
    return __ldg((const float4*)p);
}

__device__ __forceinline__ void mma_bf16(float d[4], const uint32_t a[4], const uint32_t b[2]) {
    asm volatile(
        "mma.sync.aligned.m16n8k16.row.col.f32.bf16.bf16.f32 "
        "{%0,%1,%2,%3}, {%4,%5,%6,%7}, {%8,%9}, {%0,%1,%2,%3};\n"
        : "+f"(d[0]), "+f"(d[1]), "+f"(d[2]), "+f"(d[3])
        : "r"(a[0]), "r"(a[1]), "r"(a[2]), "r"(a[3]), "r"(b[0]), "r"(b[1]));
}

// ---------------- merged setup: weights, bias, bounds, Z init -----------------
__global__ void k_setup(const float* __restrict__ W_ih, const float* __restrict__ W_hh,
                        const float* __restrict__ b_ih, const float* __restrict__ b_hh,
                        const int* __restrict__ batch, const float* __restrict__ qstar,
                        int n) {
    int idx = blockIdx.x * blockDim.x + threadIdx.x;
    const int RW1 = GDIM * KB1;
    const int RW2 = RW1 + GDIM * KB2;
    const int RB  = RW2 + GDIM;
    const int RS  = RB + n;
    const int RZ1 = RS + NB * KA1;
    const int RC  = RZ1 + NB * NF;
    const int RZ2 = RC + NB * 96;
    if (idx < RW1) {
        int jp = idx / KB1, u = idx % KB1;
        int j = (jp & 3) * 200 + (jp >> 2);
        int s = u / SEC1, k = u % SEC1;
        float a = 0.f;
        if (k < 400)      a = W_ih[j * 400 + k];
        else if (k < 600) a = W_hh[j * 200 + (k - 400)];
        __nv_bfloat16 hi = __float2bfloat16(a);
        g_Wb1[idx] = (s < 2) ? hi : __float2bfloat16(a - __bfloat162float(hi));
    } else if (idx < RW2) {
        int t = idx - RW1;
        int jp = t / KB2, u = t % KB2;
        int j = (jp & 3) * 200 + (jp >> 2);
        int s = u / SEC2, k = u % SEC2;
        float a = 0.f;
        if (k < 400) {
            a = W_ih[j * 400 + k];
            if (k < 200) a += W_hh[j * 200 + k];
        }
        __nv_bfloat16 hi = __float2bfloat16(a);
        g_Wb2[t] = (s < 2) ? hi : __float2bfloat16(a - __bfloat162float(hi));
    } else if (idx < RB) {
        int jp = idx - RW2;
        int j = (jp & 3) * 200 + (jp >> 2);
        g_biasP[jp] = b_ih[j] + b_hh[j];
    } else if (idx < RS) {
        int i = idx - RB;
        int b = batch[i];
        if (i == 0) { for (int q = 0; q <= b; ++q) g_seg[q] = 0; }
        else {
            int pb = batch[i - 1];
            for (int q = pb + 1; q <= b; ++q) g_seg[q] = i;
        }
        if (i == n - 1) { for (int q = b + 1; q <= NB; ++q) g_seg[q] = n; }
    } else if (idx < RZ1) {
        int t = idx - RS;
        int b = t / KA1, u = t % KA1;
        int s = u / SEC1, k = u % SEC1;     // s in {0,1}
        if (k < 400) {
            float v = qstar[b * 400 + k];
            __nv_bfloat16 hi = __float2bfloat16(v);
            g_Zb1[t] = (s == 1) ? __float2bfloat16(v - __bfloat162float(hi)) : hi;
        } else if (k >= 600) {
            g_Zb1[t] = __float2bfloat16(0.f);
        } // 400..599 written by k_h0
    } else if (idx < RC) {
        g_C[idx - RZ1] = 0.f;
    } else if (idx < RZ2) {
        int t = idx - RC;
        int b = t / 96, k = t % 96;
        int sec = k / 48;                   // sections 0,1 only
        g_Zb2[b * KA2 + sec * SEC2 + 400 + (k % 48)] = __float2bfloat16(0.f);
    }
}

// ---------------- h0 = segment_sum(cos*x) → Zb1 h sections --------------------
__global__ void __launch_bounds__(256) k_h0(const float* __restrict__ x,
                                            const float* __restrict__ cosc) {
    __shared__ float part[8][NF];
    int b = blockIdx.x;
    int s0 = g_seg[b], s1 = g_seg[b + 1];
    int tid = threadIdx.x, lane = tid & 31, wid = tid >> 5;

    float4 aA = make_float4(0.f, 0.f, 0.f, 0.f);
    float4 aB = make_float4(0.f, 0.f, 0.f, 0.f);
    for (int n = s0 + wid; n < s1; n += 8) {
        float c = __ldg(cosc + n);
        const float* rp = x + (size_t)n * NF;
        float4 v = ld4(rp + 4 * lane);
        aA.x += c * v.x; aA.y += c * v.y; aA.z += c * v.z; aA.w += c * v.w;
        if (lane < 18) {
            float4 v2 = ld4(rp + 128 + 4 * lane);
            aB.x += c * v2.x; aB.y += c * v2.y; aB.z += c * v2.z; aB.w += c * v2.w;
        }
    }
    part[wid][4 * lane + 0] = aA.x; part[wid][4 * lane + 1] = aA.y;
    part[wid][4 * lane + 2] = aA.z; part[wid][4 * lane + 3] = aA.w;
    if (lane < 18) {
        part[wid][128 + 4 * lane + 0] = aB.x; part[wid][128 + 4 * lane + 1] = aB.y;
        part[wid][128 + 4 * lane + 2] = aB.z; part[wid][128 + 4 * lane + 3] = aB.w;
    }
    __syncthreads();
    if (tid < NF) {
        float s = 0.f;
#pragma unroll
        for (int w = 0; w < 8; ++w) s += part[w][tid];
        __nv_bfloat16 hi = __float2bfloat16(s);
        __nv_bfloat16 lo = __float2bfloat16(s - __bfloat162float(hi));
        size_t base = (size_t)b * KA1;
        g_Zb1[base + 400 + tid] = hi;
        g_Zb1[base + SEC1 + 400 + tid] = lo;
    }
}

// --- split-K mma.sync bf16 GEMM (CTA 128x80, 2 K-splits, 2 stages, occ 3) ------
// Grid: x = n-block, y = m-block → co-resident CTAs share the A tile (L1 via .ca)
template<int KBW, int KA, int SECC, int NCHUNK>
__global__ void __launch_bounds__(256, 3) k_gemm_split(const __nv_bfloat16* __restrict__ A,
                                                       const __nv_bfloat16* __restrict__ Wb) {
    extern __shared__ char smem[];
    uint32_t sbase = smem_u32(smem);
    int tid = threadIdx.x, lane = tid & 31, warp = tid >> 5;
    int m0 = blockIdx.y * GM;
    int n0 = blockIdx.x * GNT;
    int z  = blockIdx.z;
    int c0 = (z * NCHUNK) / NSPLIT, c1 = ((z + 1) * NCHUNK) / NSPLIT;

    int wm = warp >> 1, wn = warp & 1;
    int r7 = lane & 7, quad = lane >> 3;
    int gg = lane >> 2, t4 = lane & 3;

    float acc[2][5][4];
#pragma unroll
    for (int t = 0; t < 2; ++t)
#pragma unroll
        for (int u = 0; u < 5; ++u)
#pragma unroll
            for (int v = 0; v < 4; ++v) acc[t][u][v] = 0.f;

    auto load_chunk = [&](int c) {
        int s = (c - c0) % NSTAGE;
        int ca = (c < 2 * SECC) ? c : (c - 2 * SECC);   // dedup remap
        uint32_t aBase = sbase + SOFF + s * STG;
        uint32_t bBase = aBase + 16384;
        const __nv_bfloat16* gA = A + (size_t)m0 * KA + ca * 64;
        const __nv_bfloat16* gW = Wb + (size_t)n0 * KBW + c * 64;
#pragma unroll
        for (int i = 0; i < 4; ++i) {
            int t = tid + i * 256;
            int r = t >> 3, v = t & 7;
            uint32_t bo = (uint32_t)r * 128 + v * 16;
            cp16ca(aBase + (bo ^ ((r & 7) << 4)), gA + (size_t)r * KA + v * 8);
        }
        for (int t = tid; t < 80 * 8; t += 256) {
            int r = t >> 3, v = t & 7;
            uint32_t bo = (uint32_t)r * 128 + v * 16;
            cp16cg(bBase + (bo ^ ((r & 7) << 4)), gW + (size_t)r * KBW + v * 8);
        }
        CP_COMMIT();
    };

    auto compute = [&](int slot) {
        uint32_t aB = sbase + SOFF + slot * STG;
        uint32_t bB = aB + 16384;
#pragma unroll
        for (int k16 = 0; k16 < 4; ++k16) {
            int kb = k16 * 32;
            uint32_t aF[2][4], bF[5][2];
#pragma unroll
            for (int t = 0; t < 2; ++t) {
                int row = wm * 32 + t * 16 + (quad & 1) * 8 + r7;
                int cb = kb + (quad >> 1) * 16;
                uint32_t ad = aB + (((uint32_t)row * 128 + cb) ^ ((row & 7) << 4));
                asm volatile("ldmatrix.sync.aligned.m8n8.x4.shared.b16 {%0,%1,%2,%3}, [%4];"
                             : "=r"(aF[t][0]), "=r"(aF[t][1]), "=r"(aF[t][2]), "=r"(aF[t][3])
                             : "r"(ad));
            }
#pragma unroll
            for (int p = 0; p < 2; ++p) {
                int row = wn * 40 + (2 * p + (quad >> 1)) * 8 + r7;
                int cb = kb + (quad & 1) * 16;
                uint32_t bd = bB + (((uint32_t)row * 128 + cb) ^ ((row & 7) << 4));
                asm volatile("ldmatrix.sync.aligned.m8n8.x4.shared.b16 {%0,%1,%2,%3}, [%4];"
                             : "=r"(bF[2 * p][0]), "=r"(bF[2 * p][1]),
                               "=r"(bF[2 * p + 1][0]), "=r"(bF[2 * p + 1][1])
                             : "r"(bd));
            }
            {
                int row = wn * 40 + 32 + r7;
                int cb = kb + (quad & 1) * 16;
                uint32_t bd = bB + (((uint32_t)row * 128 + cb) ^ ((row & 7) << 4));
                asm volatile("ldmatrix.sync.aligned.m8n8.x2.shared.b16 {%0,%1}, [%2];"
                             : "=r"(bF[4][0]), "=r"(bF[4][1]) : "r"(bd));
            }
#pragma unroll
            for (int t = 0; t < 2; ++t)
#pragma unroll
                for (int u = 0; u < 5; ++u) mma_bf16(acc[t][u], aF[t], bF[u]);
        }
    };

    load_chunk(c0);
    if (c0 + 1 < c1) load_chunk(c0 + 1);
    for (int c = c0; c < c1; ++c) {
        if (c + 1 < c1) asm volatile("cp.async.wait_group 1;" ::: "memory");
        else            asm volatile("cp.async.wait_group 0;" ::: "memory");
        __syncthreads();
        compute((c - c0) % NSTAGE);
        if (c + 2 < c1) {
            __syncthreads();              // stage free before overwrite
            load_chunk(c + 2);
        }
    }

    // write partials
    float* Gp = g_Gp + (size_t)z * NB * GDIM;
#pragma unroll
    for (int t = 0; t < 2; ++t)
#pragma unroll
        for (int u = 0; u < 5; ++u) {
            int row = m0 + wm * 32 + t * 16 + gg;
            int col = n0 + wn * 40 + u * 8 + 2 * t4;
            *(float2*)(Gp + (size_t)row * GDIM + col)       = make_float2(acc[t][u][0], acc[t][u][1]);
            *(float2*)(Gp + (size_t)(row + 8) * GDIM + col) = make_float2(acc[t][u][2], acc[t][u][3]);
        }
}

// --- fused: split-K reduce + LSTM pointwise (prologue) + shifted-exp softmax ---
__global__ void __launch_bounds__(256) k_attn(const float* __restrict__ x,
                                              float* __restrict__ out, int writeOut) {
    __shared__ float qs[208];
    __shared__ float part[8][NF];
    __shared__ float ps[8];

    int b = blockIdx.x;
    int s0 = g_seg[b], s1 = g_seg[b + 1];
    int tid = threadIdx.x, lane = tid & 31, wid = tid >> 5;

    // ---- prologue: sum 2 split-K partials, LSTM pointwise → q (row b) --------
    if (tid < NF) {
        const float* p0 = g_Gp + (size_t)b * GDIM + 4 * tid;
        float4 s = *(const float4*)p0;
#pragma unroll
        for (int z = 1; z < NSPLIT; ++z) {
            float4 t = *(const float4*)(p0 + (size_t)z * NB * GDIM);
            s.x += t.x; s.y += t.y; s.z += t.z; s.w += t.w;
        }
        const float4 bb = *(const float4*)(g_biasP + 4 * tid);
        float i_ = s.x + bb.x;
        float f_ = s.y + bb.y;
        float g_ = s.z + bb.z;
        float o_ = s.w + bb.w;
        float c = g_C[(size_t)b * NF + tid];
        c = sigmoidf_(f_) * c + sigmoidf_(i_) * tanhf(g_);
        float h = sigmoidf_(o_) * tanhf(c);
        g_C[(size_t)b * NF + tid] = c;
        qs[tid] = h;
        __nv_bfloat16 hi = __float2bfloat16(h);
        __nv_bfloat16 lo = __float2bfloat16(h - __bfloat162float(hi));
        __nv_bfloat16* Zr = g_Zb2 + (size_t)b * KA2;
        Zr[tid] = hi; Zr[SEC2 + tid] = lo;
    }
    __syncthreads();

    const float4* q4 = (const float4*)qs;
    float4 qa = q4[lane];
    float4 qb = make_float4(0.f, 0.f, 0.f, 0.f);
    if (lane < 18) qb = q4[32 + lane];

    float4 ra = make_float4(0.f, 0.f, 0.f, 0.f);
    float4 rb = make_float4(0.f, 0.f, 0.f, 0.f);
    float run_s = 0.f;

    // streaming loop: two rows per iteration per warp, branch-free weights
    for (int n = s0 + wid; n < s1; n += 16) {
        int n2 = n + 8;
        bool has2 = (n2 < s1);
        const float* rp = x + (size_t)n * NF;
        float4 va = ld4(rp + 4 * lane);
        float4 vb = make_float4(0.f, 0.f, 0.f, 0.f);
        float4 wa = make_float4(0.f, 0.f, 0.f, 0.f);
        float4 wb = make_float4(0.f, 0.f, 0.f, 0.f);
        if (has2) {
            const float* rp2 = x + (size_t)n2 * NF;
            wa = ld4(rp2 + 4 * lane);
            if (lane < 18) wb = ld4(rp2 + 128 + 4 * lane);
        }
        float p = va.x * qa.x + va.y * qa.y + va.z * qa.z + va.w * qa.w;
        float p2 = wa.x * qa.x + wa.y * qa.y + wa.z * qa.z + wa.w * qa.w;
        if (lane < 18) {
            vb = ld4(rp + 128 + 4 * lane);
            p += vb.x * qb.x + vb.y * qb.y + vb.z * qb.z + vb.w * qb.w;
            p2 += wb.x * qb.x + wb.y * qb.y + wb.z * qb.z + wb.w * qb.w;
        }
#pragma unroll
        for (int o = 16; o > 0; o >>= 1) {
            p  += __shfl_xor_sync(0xffffffffu, p, o);
            p2 += __shfl_xor_sync(0xffffffffu, p2, o);
        }
        float w = __expf(p - ESHIFT);
        run_s += w;
        ra.x += w * va.x; ra.y += w * va.y; ra.z += w * va.z; ra.w += w * va.w;
        rb.x += w * vb.x; rb.y += w * vb.y; rb.z += w * vb.z; rb.w += w * vb.w;
        if (has2) {
            float w2 = __expf(p2 - ESHIFT);
            run_s += w2;
            ra.x += w2 * wa.x; ra.y += w2 * wa.y; ra.z += w2 * wa.z; ra.w += w2 * wa.w;
            rb.x += w2 * wb.x; rb.y += w2 * wb.y; rb.z += w2 * wb.z; rb.w += w2 * wb.w;
        }
    }

    part[wid][4 * lane + 0] = ra.x; part[wid][4 * lane + 1] = ra.y;
    part[wid][4 * lane + 2] = ra.z; part[wid][4 * lane + 3] = ra.w;
    if (lane < 18) {
        part[wid][128 + 4 * lane + 0] = rb.x; part[wid][128 + 4 * lane + 1] = rb.y;
        part[wid][128 + 4 * lane + 2] = rb.z; part[wid][128 + 4 * lane + 3] = rb.w;
    }
    if (lane == 0) ps[wid] = run_s;
    __syncthreads();

    if (tid < NF) {
        float denom = 0.f, r = 0.f;
#pragma unroll
        for (int w = 0; w < 8; ++w) {
            denom += ps[w];
            r     += part[w][tid];
        }
        r = (denom > 0.f) ? (r / denom) : 0.f;
        __nv_bfloat16 hi = __float2bfloat16(r);
        __nv_bfloat16 lo = __float2bfloat16(r - __bfloat162float(hi));
        size_t base = (size_t)b * KA2 + 200 + tid;
        g_Zb2[base] = hi;
        g_Zb2[base + SEC2] = lo;
        if (writeOut) {
            out[b * 400 + tid] = qs[tid];
            out[b * 400 + 200 + tid] = r;
        }
    }
}

// ---------------- launch ---------------------------------------------------------
extern "C" void kernel_launch(void* const* d_in, const int* in_sizes, int n_in,
                              void* d_out, int out_size) {
    const float* x     = (const float*)d_in[0];
    const int*   batch = (const int*)  d_in[1];
    const float* cosc  = (const float*)d_in[2];
    const float* qstar = (const float*)d_in[3];
    const float* W_ih  = (const float*)d_in[4];
    const float* W_hh  = (const float*)d_in[5];
    const float* b_ih  = (const float*)d_in[6];
    const float* b_hh  = (const float*)d_in[7];
    float* out = (float*)d_out;

    int n = in_sizes[1];

    const int smemBytes = SOFF + NSTAGE * STG;   // 54272
    cudaFuncSetAttribute((const void*)k_gemm_split<KB1, KA1, SECC1, NCH1>,
                         cudaFuncAttributeMaxDynamicSharedMemorySize, smemBytes);
    cudaFuncSetAttribute((const void*)k_gemm_split<KB2, KA2, SECC2, NCH2>,
                         cudaFuncAttributeMaxDynamicSharedMemorySize, smemBytes);

    __nv_bfloat16 *zb1, *zb2, *wb1, *wb2;
    cudaGetSymbolAddress((void**)&zb1, g_Zb1);
    cudaGetSymbolAddress((void**)&zb2, g_Zb2);
    cudaGetSymbolAddress((void**)&wb1, g_Wb1);
    cudaGetSymbolAddress((void**)&wb2, g_Wb2);

    const int setupTot = GDIM * KB1 + GDIM * KB2 + GDIM + n + NB * KA1 + NB * NF + NB * 96;
    k_setup<<<(setupTot + 255) / 256, 256>>>(W_ih, W_hh, b_ih, b_hh, batch, qstar, n);
    k_h0   <<<NB, 256>>>(x, cosc);

    dim3 ggrid(GDIM / GNT, NB / GM, NSPLIT);     // x=n(10), y=m(16), z=split: A shared per SM
    for (int s = 0; s < STEPS; ++s) {
        if (s == 0) k_gemm_split<KB1, KA1, SECC1, NCH1><<<ggrid, 256, smemBytes>>>(zb1, wb1);
        else        k_gemm_split<KB2, KA2, SECC2, NCH2><<<ggrid, 256, smemBytes>>>(zb2, wb2);
        k_attn<<<NB, 256>>>(x, out, s == STEPS - 1 ? 1 : 0);
    }
}

// round 16
// speedup vs baseline: 1.0547x; 1.0547x over previous
#include <cuda_runtime.h>
#include <cuda_bf16.h>
#include <cstdint>

// Problem constants
#define NTOT 131072
#define NB   2048
#define NF   200
#define GDIM 800
#define STEPS 3

// bf16x3 via K-concatenation: W = [bH | bH | bL] (3 sections),
// A stored deduped as [aH | aL] (2 sections); chunk c>=2*SECC remaps to aH.
#define KB1 1920
#define KB2 1344
#define KA1 1280
#define KA2 896
#define SEC1 640
#define SEC2 448
#define SECC1 10
#define SECC2 7
#define NCH1 30
#define NCH2 21
#define GM 128
#define GNT 80
#define NSPLIT 2
#define NSTAGE 2
#define STG 26624        // A 128x64 bf16 (16384) + B 80x64 bf16 (10240)
#define SOFF 1024
#define ESHIFT 16.0f     // constant softmax shift (exact algebra, overflow guard)

// ---------------- scratch ----------------------------------------------------
__device__ __nv_bfloat16 g_Zb1[NB * KA1];
__device__ __nv_bfloat16 g_Zb2[NB * KA2];
__device__ __nv_bfloat16 g_Wb1[GDIM * KB1];   // permuted rows jp = unit*4+gate
__device__ __nv_bfloat16 g_Wb2[GDIM * KB2];
__device__ float g_biasP[GDIM];
__device__ float g_C[NB * NF];                // LSTM cell state
__device__ float g_Gp[NSPLIT * NB * GDIM];    // split-K partials
__device__ int   g_seg[NB + 2];

// ---------------- helpers ----------------------------------------------------
__device__ __forceinline__ uint32_t smem_u32(const void* p) {
    return (uint32_t)__cvta_generic_to_shared(p);
}
__device__ __forceinline__ float sigmoidf_(float x) { return 1.0f / (1.0f + expf(-x)); }

__device__ __forceinline__ void cp16(uint32_t dst, const void* src) {
    asm volatile("cp.async.cg.shared.global [%0], [%1], 16;" :: "r"(dst), "l"(src) : "memory");
}
#define CP_COMMIT() asm volatile("cp.async.commit_group;" ::: "memory")

__device__ __forceinline__ float4 ld4(const float* p) {
    return __ldg((const float4*)p);
}

__device__ __forceinline__ void mma_bf16(float d[4], const uint32_t a[4], const uint32_t b[2]) {
    asm volatile(
        "mma.sync.aligned.m16n8k16.row.col.f32.bf16.bf16.f32 "
        "{%0,%1,%2,%3}, {%4,%5,%6,%7}, {%8,%9}, {%0,%1,%2,%3};\n"
        : "+f"(d[0]), "+f"(d[1]), "+f"(d[2]), "+f"(d[3])
        : "r"(a[0]), "r"(a[1]), "r"(a[2]), "r"(a[3]), "r"(b[0]), "r"(b[1]));
}

__device__ __forceinline__ int lowerb(const int* __restrict__ a, int n, int v) {
    int lo = 0, hi = n;
    while (lo < hi) {
        int m = (lo + hi) >> 1;
        if (__ldg(a + m) < v) lo = m + 1; else hi = m;
    }
    return lo;
}

// ------- merged init: blocks [0,NB) = h0 (binary-search bounds); rest = setup --
__global__ void __launch_bounds__(256) k_init(const float* __restrict__ x,
                                              const float* __restrict__ cosc,
                                              const float* __restrict__ W_ih,
                                              const float* __restrict__ W_hh,
                                              const float* __restrict__ b_ih,
                                              const float* __restrict__ b_hh,
                                              const int* __restrict__ batch,
                                              const float* __restrict__ qstar,
                                              int n) {
    __shared__ float part[8][NF];
    __shared__ int sb[2];

    if (blockIdx.x >= NB) {
        // ---------------- setup portion ----------------
        int idx = (blockIdx.x - NB) * 256 + threadIdx.x;
        const int RW1 = GDIM * KB1;
        const int RW2 = RW1 + GDIM * KB2;
        const int RB  = RW2 + GDIM;
        const int RS  = RB + n;
        const int RZ1 = RS + NB * KA1;
        const int RC  = RZ1 + NB * NF;
        const int RZ2 = RC + NB * 96;
        if (idx < RW1) {
            int jp = idx / KB1, u = idx % KB1;
            int j = (jp & 3) * 200 + (jp >> 2);
            int s = u / SEC1, k = u % SEC1;
            float a = 0.f;
            if (k < 400)      a = W_ih[j * 400 + k];
            else if (k < 600) a = W_hh[j * 200 + (k - 400)];
            __nv_bfloat16 hi = __float2bfloat16(a);
            g_Wb1[idx] = (s < 2) ? hi : __float2bfloat16(a - __bfloat162float(hi));
        } else if (idx < RW2) {
            int t = idx - RW1;
            int jp = t / KB2, u = t % KB2;
            int j = (jp & 3) * 200 + (jp >> 2);
            int s = u / SEC2, k = u % SEC2;
            float a = 0.f;
            if (k < 400) {
                a = W_ih[j * 400 + k];
                if (k < 200) a += W_hh[j * 200 + k];
            }
            __nv_bfloat16 hi = __float2bfloat16(a);
            g_Wb2[t] = (s < 2) ? hi : __float2bfloat16(a - __bfloat162float(hi));
        } else if (idx < RB) {
            int jp = idx - RW2;
            int j = (jp & 3) * 200 + (jp >> 2);
            g_biasP[jp] = b_ih[j] + b_hh[j];
        } else if (idx < RS) {
            int i = idx - RB;
            int b = batch[i];
            if (i == 0) { for (int q = 0; q <= b; ++q) g_seg[q] = 0; }
            else {
                int pb = batch[i - 1];
                for (int q = pb + 1; q <= b; ++q) g_seg[q] = i;
            }
            if (i == n - 1) { for (int q = b + 1; q <= NB; ++q) g_seg[q] = n; }
        } else if (idx < RZ1) {
            int t = idx - RS;
            int b = t / KA1, u = t % KA1;
            int s = u / SEC1, k = u % SEC1;     // s in {0,1}
            if (k < 400) {
                float v = qstar[b * 400 + k];
                __nv_bfloat16 hi = __float2bfloat16(v);
                g_Zb1[t] = (s == 1) ? __float2bfloat16(v - __bfloat162float(hi)) : hi;
            } else if (k >= 600) {
                g_Zb1[t] = __float2bfloat16(0.f);
            } // 400..599 written by h0 blocks
        } else if (idx < RC) {
            g_C[idx - RZ1] = 0.f;
        } else if (idx < RZ2) {
            int t = idx - RC;
            int b = t / 96, k = t % 96;
            int sec = k / 48;
            g_Zb2[b * KA2 + sec * SEC2 + 400 + (k % 48)] = __float2bfloat16(0.f);
        }
        return;
    }

    // ---------------- h0 portion (binary-search bounds; no g_seg dep) --------
    int b = blockIdx.x;
    int tid = threadIdx.x, lane = tid & 31, wid = tid >> 5;
    if (tid < 2) sb[tid] = lowerb(batch, n, b + tid);
    __syncthreads();
    int s0 = sb[0], s1 = sb[1];

    float4 aA = make_float4(0.f, 0.f, 0.f, 0.f);
    float4 aB = make_float4(0.f, 0.f, 0.f, 0.f);
    for (int nn = s0 + wid; nn < s1; nn += 8) {
        float c = __ldg(cosc + nn);
        const float* rp = x + (size_t)nn * NF;
        float4 v = ld4(rp + 4 * lane);
        aA.x += c * v.x; aA.y += c * v.y; aA.z += c * v.z; aA.w += c * v.w;
        if (lane < 18) {
            float4 v2 = ld4(rp + 128 + 4 * lane);
            aB.x += c * v2.x; aB.y += c * v2.y; aB.z += c * v2.z; aB.w += c * v2.w;
        }
    }
    part[wid][4 * lane + 0] = aA.x; part[wid][4 * lane + 1] = aA.y;
    part[wid][4 * lane + 2] = aA.z; part[wid][4 * lane + 3] = aA.w;
    if (lane < 18) {
        part[wid][128 + 4 * lane + 0] = aB.x; part[wid][128 + 4 * lane + 1] = aB.y;
        part[wid][128 + 4 * lane + 2] = aB.z; part[wid][128 + 4 * lane + 3] = aB.w;
    }
    __syncthreads();
    if (tid < NF) {
        float s = 0.f;
#pragma unroll
        for (int w = 0; w < 8; ++w) s += part[w][tid];
        __nv_bfloat16 hi = __float2bfloat16(s);
        __nv_bfloat16 lo = __float2bfloat16(s - __bfloat162float(hi));
        size_t base = (size_t)b * KA1;
        g_Zb1[base + 400 + tid] = hi;
        g_Zb1[base + SEC1 + 400 + tid] = lo;
    }
}

// --- split-K mma.sync bf16 GEMM (CTA 128x80, 2 K-splits, 2 stages, occ 3) ------
// A is deduped: chunks >= 2*SECC reuse the aH section (chunk c - 2*SECC).
template<int KBW, int KA, int SECC, int NCHUNK>
__global__ void __launch_bounds__(256, 3) k_gemm_split(const __nv_bfloat16* __restrict__ A,
                                                       const __nv_bfloat16* __restrict__ Wb) {
    extern __shared__ char smem[];
    uint32_t sbase = smem_u32(smem);
    int tid = threadIdx.x, lane = tid & 31, warp = tid >> 5;
    int m0 = blockIdx.x * GM;
    int n0 = blockIdx.y * GNT;
    int z  = blockIdx.z;
    int c0 = (z * NCHUNK) / NSPLIT, c1 = ((z + 1) * NCHUNK) / NSPLIT;

    int wm = warp >> 1, wn = warp & 1;
    int r7 = lane & 7, quad = lane >> 3;
    int gg = lane >> 2, t4 = lane & 3;

    float acc[2][5][4];
#pragma unroll
    for (int t = 0; t < 2; ++t)
#pragma unroll
        for (int u = 0; u < 5; ++u)
#pragma unroll
            for (int v = 0; v < 4; ++v) acc[t][u][v] = 0.f;

    auto load_chunk = [&](int c) {
        int s = (c - c0) % NSTAGE;
        int ca = (c < 2 * SECC) ? c : (c - 2 * SECC);   // dedup remap
        uint32_t aBase = sbase + SOFF + s * STG;
        uint32_t bBase = aBase + 16384;
        const __nv_bfloat16* gA = A + (size_t)m0 * KA + ca * 64;
        const __nv_bfloat16* gW = Wb + (size_t)n0 * KBW + c * 64;
#pragma unroll
        for (int i = 0; i < 4; ++i) {
            int t = tid + i * 256;
            int r = t >> 3, v = t & 7;
            uint32_t bo = (uint32_t)r * 128 + v * 16;
            cp16(aBase + (bo ^ ((r & 7) << 4)), gA + (size_t)r * KA + v * 8);
        }
        for (int t = tid; t < 80 * 8; t += 256) {
            int r = t >> 3, v = t & 7;
            uint32_t bo = (uint32_t)r * 128 + v * 16;
            cp16(bBase + (bo ^ ((r & 7) << 4)), gW + (size_t)r * KBW + v * 8);
        }
        CP_COMMIT();
    };

    auto compute = [&](int slot) {
        uint32_t aB = sbase + SOFF + slot * STG;
        uint32_t bB = aB + 16384;
#pragma unroll
        for (int k16 = 0; k16 < 4; ++k16) {
            int kb = k16 * 32;
            uint32_t aF[2][4], bF[5][2];
#pragma unroll
            for (int t = 0; t < 2; ++t) {
                int row = wm * 32 + t * 16 + (quad & 1) * 8 + r7;
                int cb = kb + (quad >> 1) * 16;
                uint32_t ad = aB + (((uint32_t)row * 128 + cb) ^ ((row & 7) << 4));
                asm volatile("ldmatrix.sync.aligned.m8n8.x4.shared.b16 {%0,%1,%2,%3}, [%4];"
                             : "=r"(aF[t][0]), "=r"(aF[t][1]), "=r"(aF[t][2]), "=r"(aF[t][3])
                             : "r"(ad));
            }
#pragma unroll
            for (int p = 0; p < 2; ++p) {
                int row = wn * 40 + (2 * p + (quad >> 1)) * 8 + r7;
                int cb = kb + (quad & 1) * 16;
                uint32_t bd = bB + (((uint32_t)row * 128 + cb) ^ ((row & 7) << 4));
                asm volatile("ldmatrix.sync.aligned.m8n8.x4.shared.b16 {%0,%1,%2,%3}, [%4];"
                             : "=r"(bF[2 * p][0]), "=r"(bF[2 * p][1]),
                               "=r"(bF[2 * p + 1][0]), "=r"(bF[2 * p + 1][1])
                             : "r"(bd));
            }
            {
                int row = wn * 40 + 32 + r7;
                int cb = kb + (quad & 1) * 16;
                uint32_t bd = bB + (((uint32_t)row * 128 + cb) ^ ((row & 7) << 4));
                asm volatile("ldmatrix.sync.aligned.m8n8.x2.shared.b16 {%0,%1}, [%2];"
                             : "=r"(bF[4][0]), "=r"(bF[4][1]) : "r"(bd));
            }
#pragma unroll
            for (int t = 0; t < 2; ++t)
#pragma unroll
                for (int u = 0; u < 5; ++u) mma_bf16(acc[t][u], aF[t], bF[u]);
        }
    };

    load_chunk(c0);
    if (c0 + 1 < c1) load_chunk(c0 + 1);
    for (int c = c0; c < c1; ++c) {
        if (c + 1 < c1) asm volatile("cp.async.wait_group 1;" ::: "memory");
        else            asm volatile("cp.async.wait_group 0;" ::: "memory");
        __syncthreads();
        compute((c - c0) % NSTAGE);
        if (c + 2 < c1) {
            __syncthreads();              // stage free before overwrite
            load_chunk(c + 2);
        }
    }

    // write partials
    float* Gp = g_Gp + (size_t)z * NB * GDIM;
#pragma unroll
    for (int t = 0; t < 2; ++t)
#pragma unroll
        for (int u = 0; u < 5; ++u) {
            int row = m0 + wm * 32 + t * 16 + gg;
            int col = n0 + wn * 40 + u * 8 + 2 * t4;
            *(float2*)(Gp + (size_t)row * GDIM + col)       = make_float2(acc[t][u][0], acc[t][u][1]);
            *(float2*)(Gp + (size_t)(row + 8) * GDIM + col) = make_float2(acc[t][u][2], acc[t][u][3]);
        }
}

// --- fused: split-K reduce + LSTM pointwise (prologue) + shifted-exp softmax ---
__global__ void __launch_bounds__(256) k_attn(const float* __restrict__ x,
                                              float* __restrict__ out, int writeOut) {
    __shared__ float qs[208];
    __shared__ float part[8][NF];
    __shared__ float ps[8];

    int b = blockIdx.x;
    int s0 = g_seg[b], s1 = g_seg[b + 1];
    int tid = threadIdx.x, lane = tid & 31, wid = tid >> 5;

    // ---- prologue: sum 2 split-K partials, LSTM pointwise → q (row b) --------
    if (tid < NF) {
        const float* p0 = g_Gp + (size_t)b * GDIM + 4 * tid;
        float4 s = *(const float4*)p0;
#pragma unroll
        for (int z = 1; z < NSPLIT; ++z) {
            float4 t = *(const float4*)(p0 + (size_t)z * NB * GDIM);
            s.x += t.x; s.y += t.y; s.z += t.z; s.w += t.w;
        }
        const float4 bb = *(const float4*)(g_biasP + 4 * tid);
        float i_ = s.x + bb.x;
        float f_ = s.y + bb.y;
        float g_ = s.z + bb.z;
        float o_ = s.w + bb.w;
        float c = g_C[(size_t)b * NF + tid];
        c = sigmoidf_(f_) * c + sigmoidf_(i_) * tanhf(g_);
        float h = sigmoidf_(o_) * tanhf(c);
        g_C[(size_t)b * NF + tid] = c;
        qs[tid] = h;
        __nv_bfloat16 hi = __float2bfloat16(h);
        __nv_bfloat16 lo = __float2bfloat16(h - __bfloat162float(hi));
        __nv_bfloat16* Zr = g_Zb2 + (size_t)b * KA2;
        Zr[tid] = hi; Zr[SEC2 + tid] = lo;
    }
    __syncthreads();

    const float4* q4 = (const float4*)qs;
    float4 qa = q4[lane];
    float4 qb = make_float4(0.f, 0.f, 0.f, 0.f);
    if (lane < 18) qb = q4[32 + lane];

    float4 ra = make_float4(0.f, 0.f, 0.f, 0.f);
    float4 rb = make_float4(0.f, 0.f, 0.f, 0.f);
    float run_s = 0.f;

    // streaming loop: two rows per iteration per warp, branch-free weights
    for (int n = s0 + wid; n < s1; n += 16) {
        int n2 = n + 8;
        bool has2 = (n2 < s1);
        const float* rp = x + (size_t)n * NF;
        float4 va = ld4(rp + 4 * lane);
        float4 vb = make_float4(0.f, 0.f, 0.f, 0.f);
        float4 wa = make_float4(0.f, 0.f, 0.f, 0.f);
        float4 wb = make_float4(0.f, 0.f, 0.f, 0.f);
        if (has2) {
            const float* rp2 = x + (size_t)n2 * NF;
            wa = ld4(rp2 + 4 * lane);
            if (lane < 18) wb = ld4(rp2 + 128 + 4 * lane);
        }
        float p = va.x * qa.x + va.y * qa.y + va.z * qa.z + va.w * qa.w;
        float p2 = wa.x * qa.x + wa.y * qa.y + wa.z * qa.z + wa.w * qa.w;
        if (lane < 18) {
            vb = ld4(rp + 128 + 4 * lane);
            p += vb.x * qb.x + vb.y * qb.y + vb.z * qb.z + vb.w * qb.w;
            p2 += wb.x * qb.x + wb.y * qb.y + wb.z * qb.z + wb.w * qb.w;
        }
#pragma unroll
        for (int o = 16; o > 0; o >>= 1) {
            p  += __shfl_xor_sync(0xffffffffu, p, o);
            p2 += __shfl_xor_sync(0xffffffffu, p2, o);
        }
        float w = __expf(p - ESHIFT);
        run_s += w;
        ra.x += w * va.x; ra.y += w * va.y; ra.z += w * va.z; ra.w += w * va.w;
        rb.x += w * vb.x; rb.y += w * vb.y; rb.z += w * vb.z; rb.w += w * vb.w;
        if (has2) {
            float w2 = __expf(p2 - ESHIFT);
            run_s += w2;
            ra.x += w2 * wa.x; ra.y += w2 * wa.y; ra.z += w2 * wa.z; ra.w += w2 * wa.w;
            rb.x += w2 * wb.x; rb.y += w2 * wb.y; rb.z += w2 * wb.z; rb.w += w2 * wb.w;
        }
    }

    part[wid][4 * lane + 0] = ra.x; part[wid][4 * lane + 1] = ra.y;
    part[wid][4 * lane + 2] = ra.z; part[wid][4 * lane + 3] = ra.w;
    if (lane < 18) {
        part[wid][128 + 4 * lane + 0] = rb.x; part[wid][128 + 4 * lane + 1] = rb.y;
        part[wid][128 + 4 * lane + 2] = rb.z; part[wid][128 + 4 * lane + 3] = rb.w;
    }
    if (lane == 0) ps[wid] = run_s;
    __syncthreads();

    if (tid < NF) {
        float denom = 0.f, r = 0.f;
#pragma unroll
        for (int w = 0; w < 8; ++w) {
            denom += ps[w];
            r     += part[w][tid];
        }
        r = (denom > 0.f) ? (r / denom) : 0.f;
        __nv_bfloat16 hi = __float2bfloat16(r);
        __nv_bfloat16 lo = __float2bfloat16(r - __bfloat162float(hi));
        size_t base = (size_t)b * KA2 + 200 + tid;
        g_Zb2[base] = hi;
        g_Zb2[base + SEC2] = lo;
        if (writeOut) {
            out[b * 400 + tid] = qs[tid];
            out[b * 400 + 200 + tid] = r;
        }
    }
}

// ---------------- launch ---------------------------------------------------------
extern "C" void kernel_launch(void* const* d_in, const int* in_sizes, int n_in,
                              void* d_out, int out_size) {
    const float* x     = (const float*)d_in[0];
    const int*   batch = (const int*)  d_in[1];
    const float* cosc  = (const float*)d_in[2];
    const float* qstar = (const float*)d_in[3];
    const float* W_ih  = (const float*)d_in[4];
    const float* W_hh  = (const float*)d_in[5];
    const float* b_ih  = (const float*)d_in[6];
    const float* b_hh  = (const float*)d_in[7];
    float* out = (float*)d_out;

    int n = in_sizes[1];

    const int smemBytes = SOFF + NSTAGE * STG;   // 54272
    cudaFuncSetAttribute((const void*)k_gemm_split<KB1, KA1, SECC1, NCH1>,
                         cudaFuncAttributeMaxDynamicSharedMemorySize, smemBytes);
    cudaFuncSetAttribute((const void*)k_gemm_split<KB2, KA2, SECC2, NCH2>,
                         cudaFuncAttributeMaxDynamicSharedMemorySize, smemBytes);

    __nv_bfloat16 *zb1, *zb2, *wb1, *wb2;
    cudaGetSymbolAddress((void**)&zb1, g_Zb1);
    cudaGetSymbolAddress((void**)&zb2, g_Zb2);
    cudaGetSymbolAddress((void**)&wb1, g_Wb1);
    cudaGetSymbolAddress((void**)&wb2, g_Wb2);

    const int setupTot = GDIM * KB1 + GDIM * KB2 + GDIM + n + NB * KA1 + NB * NF + NB * 96;
    const int initBlocks = NB + (setupTot + 255) / 256;
    k_init<<<initBlocks, 256>>>(x, cosc, W_ih, W_hh, b_ih, b_hh, batch, qstar, n);

    dim3 ggrid(NB / GM, GDIM / GNT, NSPLIT);     // 16 x 10 x 2 = 320 CTAs (one wave @ occ 3)
    for (int s = 0; s < STEPS; ++s) {
        if (s == 0) k_gemm_split<KB1, KA1, SECC1, NCH1><<<ggrid, 256, smemBytes>>>(zb1, wb1);
        else        k_gemm_split<KB2, KA2, SECC2, NCH2><<<ggrid, 256, smemBytes>>>(zb2, wb2);
        k_attn<<<NB, 256>>>(x, out, s == STEPS - 1 ? 1 : 0);
    }
}